// round 2
// baseline (speedup 1.0000x reference)
#include <cuda_runtime.h>
#include <cuda_bf16.h>
#include <stdint.h>

// ---------------- problem constants ----------------
static constexpr int B_    = 16384;
static constexpr int KX    = 320;   // padded input K (288 -> 320)
static constexpr int KH    = 576;   // padded hidden K (512 + 32 z + 32 pad)
static constexpr int H     = 512;
static constexpr int M_OUT = 128;
static constexpr int NE    = 8;

// ---------------- scratch layout (single __device__ array) ----------------
static constexpr size_t OFF_XPAD = 0;
static constexpr size_t SZ_XPAD  = (size_t)B_*KX*2;
static constexpr size_t OFF_H1   = OFF_XPAD + SZ_XPAD;
static constexpr size_t SZ_HEXT  = (size_t)B_*KH*2;
static constexpr size_t OFF_H2   = OFF_H1 + SZ_HEXT;
static constexpr size_t OFF_G1   = OFF_H2 + SZ_HEXT;
static constexpr size_t SZ_G     = (size_t)B_*H*2;
static constexpr size_t OFF_G2   = OFF_G1 + SZ_G;
static constexpr size_t OFF_H3   = OFF_G2 + SZ_G;
static constexpr size_t SZ_H3    = (size_t)NE*B_*M_OUT*2;
static constexpr size_t OFF_PARA = OFF_H3 + SZ_H3;
static constexpr size_t SZ_PARA  = (size_t)B_*NE*4;
static constexpr size_t OFF_PART = OFF_PARA + SZ_PARA;
static constexpr size_t SZ_PART  = 2048*4;
static constexpr size_t OFF_INV  = OFF_PART + SZ_PART;
static constexpr size_t SZ_INV   = 256;
static constexpr size_t OFF_GW1T = OFF_INV + SZ_INV;
static constexpr size_t SZ_GW1T  = (size_t)H*KX*2;
static constexpr size_t OFF_GW2T = OFF_GW1T + SZ_GW1T;
static constexpr size_t SZ_GW2T  = (size_t)H*H*2;
static constexpr size_t OFF_W1T  = OFF_GW2T + SZ_GW2T;
static constexpr size_t SZ_W1T   = (size_t)NE*H*KX*2;
static constexpr size_t OFF_W2T  = OFF_W1T + SZ_W1T;
static constexpr size_t SZ_W2T   = (size_t)NE*H*KH*2;
static constexpr size_t OFF_W3T  = OFF_W2T + SZ_W2T;
static constexpr size_t SZ_W3T   = (size_t)NE*M_OUT*KH*2;
static constexpr size_t SCRATCH_TOTAL = OFF_W3T + SZ_W3T;

__device__ __align__(1024) unsigned char g_scratch[SCRATCH_TOTAL];

// ---------------- helpers ----------------
__device__ __forceinline__ uint32_t smem_u32(const void* p) {
    return (uint32_t)__cvta_generic_to_shared(p);
}
__device__ __forceinline__ uint32_t swz128(uint32_t off) {
    return off ^ ((off >> 3) & 0x70);
}
__device__ __forceinline__ void cp16(uint32_t dst, const void* src) {
    asm volatile("cp.async.cg.shared.global [%0], [%1], 16;\n" :: "r"(dst), "l"(src) : "memory");
}
__device__ __forceinline__ void ldsm_x4(uint32_t& r0, uint32_t& r1, uint32_t& r2, uint32_t& r3,
                                        uint32_t addr) {
    asm volatile("ldmatrix.sync.aligned.m8n8.x4.shared.b16 {%0,%1,%2,%3}, [%4];"
                 : "=r"(r0), "=r"(r1), "=r"(r2), "=r"(r3) : "r"(addr));
}
__device__ __forceinline__ void mma16816(float* c, uint32_t a0, uint32_t a1, uint32_t a2, uint32_t a3,
                                         uint32_t b0, uint32_t b1) {
    asm volatile(
        "mma.sync.aligned.m16n8k16.row.col.f32.bf16.bf16.f32 "
        "{%0,%1,%2,%3}, {%4,%5,%6,%7}, {%8,%9}, {%0,%1,%2,%3};"
        : "+f"(c[0]), "+f"(c[1]), "+f"(c[2]), "+f"(c[3])
        : "r"(a0), "r"(a1), "r"(a2), "r"(a3), "r"(b0), "r"(b1));
}

// ---------------- prep kernel ----------------
__global__ void prep_kernel(const float* __restrict__ motions, const float* __restrict__ z,
                            __nv_bfloat16* __restrict__ xpad,
                            __nv_bfloat16* __restrict__ h1e, __nv_bfloat16* __restrict__ h2e) {
    int idx = blockIdx.x * 256 + threadIdx.x;
    const int XT = B_ * KX;
    const int ZT = B_ * 64;
    if (idx < XT) {
        int row = idx / KX, c = idx % KX;
        float v = 0.f;
        if (c < 256)      v = motions[(size_t)row * 256 + c];
        else if (c < 288) v = z[(size_t)row * 32 + (c - 256)];
        xpad[idx] = __float2bfloat16(v);
    } else {
        int j = idx - XT;
        int which = j / ZT; j %= ZT;
        int row = j / 64, c = j % 64;
        __nv_bfloat16 v = __float2bfloat16(c < 32 ? z[(size_t)row * 32 + c] : 0.f);
        __nv_bfloat16* dst = which ? h2e : h1e;
        dst[(size_t)row * KH + 512 + c] = v;
    }
}

// ---------------- weight convert/transpose/pad kernel ----------------
static constexpr int WC_C0 = H * KX;
static constexpr int WC_C1 = H * H;
static constexpr int WC_C2 = NE * H * KX;
static constexpr int WC_C3 = NE * H * KH;
static constexpr int WC_C4 = NE * M_OUT * KH;
static constexpr int WC_TOT = WC_C0 + WC_C1 + WC_C2 + WC_C3 + WC_C4;

__global__ void wconv_kernel(const float* __restrict__ gw1, const float* __restrict__ gw2,
                             const float* __restrict__ W1, const float* __restrict__ W2,
                             const float* __restrict__ W3,
                             __nv_bfloat16* __restrict__ gw1t, __nv_bfloat16* __restrict__ gw2t,
                             __nv_bfloat16* __restrict__ W1t, __nv_bfloat16* __restrict__ W2t,
                             __nv_bfloat16* __restrict__ W3t) {
    int idx = blockIdx.x * 256 + threadIdx.x;
    if (idx < WC_C0) {
        int n = idx / KX, k = idx % KX;
        gw1t[idx] = __float2bfloat16(k < 288 ? gw1[(size_t)k * H + n] : 0.f);
        return;
    }
    idx -= WC_C0;
    if (idx < WC_C1) {
        int n = idx / H, k = idx % H;
        gw2t[idx] = __float2bfloat16(gw2[(size_t)k * H + n]);
        return;
    }
    idx -= WC_C1;
    if (idx < WC_C2) {
        int e = idx / (H * KX); int r = idx % (H * KX); int n = r / KX, k = r % KX;
        W1t[idx] = __float2bfloat16(k < 288 ? W1[((size_t)e * 288 + k) * H + n] : 0.f);
        return;
    }
    idx -= WC_C2;
    if (idx < WC_C3) {
        int e = idx / (H * KH); int r = idx % (H * KH); int n = r / KH, k = r % KH;
        W2t[idx] = __float2bfloat16(k < 544 ? W2[((size_t)e * 544 + k) * H + n] : 0.f);
        return;
    }
    idx -= WC_C3;
    if (idx < WC_C4) {
        int e = idx / (M_OUT * KH); int r = idx % (M_OUT * KH); int n = r / KH, k = r % KH;
        W3t[idx] = __float2bfloat16(k < 544 ? W3[((size_t)e * 544 + k) * M_OUT + n] : 0.f);
    }
}

// ---------------- HMMA GEMM: C[m,n] = elu(sum_k A[m,k]*Bt[n,k] + bias[n]) -> bf16 ----------------
// CTA: 256 threads, tile 128(M) x 128(N), K-chunks of 64, 2-stage cp.async.
// Warp layout: 2 (M) x 4 (N) warps; warp tile 64x32 = 4x4 m16n8k16 frags.
static constexpr int STAGE_BYTES = 16384 + 16384;              // A tile + B tile (128 x 128B each)
static constexpr int SMEM_BYTES  = 1024 + 2 * STAGE_BYTES;     // bias + 2 stages = 66560

__global__ __launch_bounds__(256)
void gemm_bias_elu(const __nv_bfloat16* __restrict__ A, int lda,
                   const __nv_bfloat16* __restrict__ Bw, int ldb,
                   const float* __restrict__ bias,
                   __nv_bfloat16* __restrict__ C, int ldc, int kchunks) {
    extern __shared__ unsigned char smem[];
    float* sbias = (float*)smem;
    unsigned char* tiles = smem + 1024;
    const uint32_t tiles_u = smem_u32(tiles);
    const int tid = threadIdx.x;
    const int m0 = blockIdx.x * 128, n0 = blockIdx.y * 128;

    if (tid < 128) sbias[tid] = bias[n0 + tid];

    // --- loader precompute: 4 x 16B per tile (A and B) per thread ---
    int lrow[4], lseg[4];
#pragma unroll
    for (int i = 0; i < 4; i++) {
        int id = tid * 4 + i;          // 0..1023
        lrow[i] = id >> 3;             // 0..127
        lseg[i] = (id & 7) * 16;       // byte seg within 128B row
    }
    const char* agbase = (const char*)(A + (size_t)m0 * lda);
    const char* bgbase = (const char*)(Bw + (size_t)n0 * ldb);
    uint32_t sdst[4];
#pragma unroll
    for (int i = 0; i < 4; i++) sdst[i] = swz128((uint32_t)(lrow[i] * 128 + lseg[i]));

    auto load_stage = [&](int s, int buf) {
        uint32_t ab = tiles_u + buf * STAGE_BYTES;
        uint32_t bb = ab + 16384;
        const char* asrc = agbase + (size_t)s * 128;   // 64 bf16 = 128B along K
        const char* bsrc = bgbase + (size_t)s * 128;
#pragma unroll
        for (int i = 0; i < 4; i++) {
            cp16(ab + sdst[i], asrc + (size_t)lrow[i] * (lda * 2) + lseg[i]);
            cp16(bb + sdst[i], bsrc + (size_t)lrow[i] * (ldb * 2) + lseg[i]);
        }
        asm volatile("cp.async.commit_group;" ::: "memory");
    };

    load_stage(0, 0);

    const int lane = tid & 31, w = tid >> 5;
    const int wm = (w >> 2) * 64;       // warp M offset (0 or 64)
    const int wn = (w & 3) * 32;        // warp N offset (0,32,64,96)

    // per-thread ldmatrix source offsets (within tile, before k offset)
    // A: row = wm + mf*16 + lane%16 ; col-half = (lane/16)*16 bytes
    // B: row = wn + p*16 + lane%16  ; col-half = (lane/16)*16 bytes (x4 covers 2 n-frags)
    const int arow = lane & 15, ahalf = (lane >> 4) * 16;

    float acc[4][4][4];
#pragma unroll
    for (int mf = 0; mf < 4; mf++)
#pragma unroll
        for (int nf = 0; nf < 4; nf++)
#pragma unroll
            for (int i = 0; i < 4; i++) acc[mf][nf][i] = 0.f;

    for (int s = 0; s < kchunks; s++) {
        if (s + 1 < kchunks) load_stage(s + 1, (s + 1) & 1);
        else asm volatile("cp.async.commit_group;" ::: "memory"); // keep group count aligned
        asm volatile("cp.async.wait_group 1;" ::: "memory");
        __syncthreads();

        uint32_t abase = tiles_u + (s & 1) * STAGE_BYTES;
        uint32_t bbase = abase + 16384;
#pragma unroll
        for (int kk = 0; kk < 4; kk++) {
            uint32_t af[4][4];
#pragma unroll
            for (int mf = 0; mf < 4; mf++) {
                uint32_t off = (uint32_t)((wm + mf * 16 + arow) * 128 + kk * 32 + ahalf);
                ldsm_x4(af[mf][0], af[mf][1], af[mf][2], af[mf][3], abase + swz128(off));
            }
            uint32_t bf[2][4];
#pragma unroll
            for (int p = 0; p < 2; p++) {
                uint32_t off = (uint32_t)((wn + p * 16 + arow) * 128 + kk * 32 + ahalf);
                ldsm_x4(bf[p][0], bf[p][1], bf[p][2], bf[p][3], bbase + swz128(off));
            }
#pragma unroll
            for (int mf = 0; mf < 4; mf++) {
#pragma unroll
                for (int p = 0; p < 2; p++) {
                    mma16816(acc[mf][2 * p],     af[mf][0], af[mf][1], af[mf][2], af[mf][3],
                             bf[p][0], bf[p][2]);
                    mma16816(acc[mf][2 * p + 1], af[mf][0], af[mf][1], af[mf][2], af[mf][3],
                             bf[p][1], bf[p][3]);
                }
            }
        }
        __syncthreads();
    }

    // ---- epilogue: bias + ELU + bf16 store ----
    const int cg = lane >> 2;            // 0..7 (row group)
    const int cc = (lane & 3) * 2;       // col pair
#pragma unroll
    for (int mf = 0; mf < 4; mf++) {
        int r0 = m0 + wm + mf * 16 + cg;
        int r1 = r0 + 8;
#pragma unroll
        for (int nf = 0; nf < 4; nf++) {
            int col = wn + nf * 8 + cc;
            float b0 = sbias[col], b1 = sbias[col + 1];
            float v0 = acc[mf][nf][0] + b0, v1 = acc[mf][nf][1] + b1;
            float v2 = acc[mf][nf][2] + b0, v3 = acc[mf][nf][3] + b1;
            v0 = v0 > 0.f ? v0 : (__expf(v0) - 1.f);
            v1 = v1 > 0.f ? v1 : (__expf(v1) - 1.f);
            v2 = v2 > 0.f ? v2 : (__expf(v2) - 1.f);
            v3 = v3 > 0.f ? v3 : (__expf(v3) - 1.f);
            *(__nv_bfloat162*)(C + (size_t)r0 * ldc + n0 + col) = __floats2bfloat162_rn(v0, v1);
            *(__nv_bfloat162*)(C + (size_t)r1 * ldc + n0 + col) = __floats2bfloat162_rn(v2, v3);
        }
    }
}

// ---------------- gate layer 3 (N=8) + deterministic partial norm ----------------
__global__ void gate3_kernel(const __nv_bfloat16* __restrict__ g2,
                             const float* __restrict__ gw3, const float* __restrict__ gb3,
                             float* __restrict__ para, float* __restrict__ partial) {
    __shared__ float sw[8 * 512];
    __shared__ float wsum[8];
    int tid = threadIdx.x;
    for (int i = tid; i < 4096; i += 256) { int k = i / 8, e = i % 8; sw[e * 512 + k] = gw3[k * 8 + e]; }
    __syncthreads();
    int warp = tid / 32, lane = tid % 32;
    int row = blockIdx.x * 8 + warp;
    float acc[8];
#pragma unroll
    for (int e = 0; e < 8; e++) acc[e] = 0.f;
    const __nv_bfloat162* gr = (const __nv_bfloat162*)(g2 + (size_t)row * 512);
#pragma unroll
    for (int i = 0; i < 8; i++) {
        __nv_bfloat162 p = gr[i * 32 + lane];
        float a0 = __bfloat162float(p.x), a1 = __bfloat162float(p.y);
        int k0 = i * 64 + lane * 2;
#pragma unroll
        for (int e = 0; e < 8; e++) acc[e] += a0 * sw[e * 512 + k0] + a1 * sw[e * 512 + k0 + 1];
    }
#pragma unroll
    for (int off = 16; off; off >>= 1)
#pragma unroll
        for (int e = 0; e < 8; e++) acc[e] += __shfl_down_sync(0xFFFFFFFFu, acc[e], off);
    if (lane == 0) {
        float ss = 0.f;
#pragma unroll
        for (int e = 0; e < 8; e++) {
            float v = acc[e] + gb3[e];
            v = v > 0.f ? v : (__expf(v) - 1.f);
            para[(size_t)row * 8 + e] = v;
            ss += v * v;
        }
        wsum[warp] = ss;
    }
    __syncthreads();
    if (tid == 0) {
        float s = 0.f;
        for (int w = 0; w < 8; w++) s += wsum[w];
        partial[blockIdx.x] = s;
    }
}

__global__ void reduce_norm_kernel(const float* __restrict__ partial, float* __restrict__ invnorm) {
    __shared__ float s[256];
    int tid = threadIdx.x;
    float v = 0.f;
    for (int k = 0; k < 8; k++) v += partial[tid + k * 256];
    s[tid] = v;
    __syncthreads();
    for (int off = 128; off; off >>= 1) {
        if (tid < off) s[tid] += s[tid + off];
        __syncthreads();
    }
    if (tid == 0) *invnorm = rsqrtf(s[0]);
}

// ---------------- combine: out = sigmoid(invnorm * sum_e para[b,e]*h3[e,b,m]) ----------------
__global__ void combine_kernel(const float* __restrict__ para, const __nv_bfloat16* __restrict__ h3,
                               const float* __restrict__ invnorm, float* __restrict__ out) {
    int t = blockIdx.x * 256 + threadIdx.x;   // t < B_*128
    int b = t >> 7;
    float inv = *invnorm;
    float4 p0 = ((const float4*)para)[b * 2];
    float4 p1 = ((const float4*)para)[b * 2 + 1];
    float pe[8] = {p0.x, p0.y, p0.z, p0.w, p1.x, p1.y, p1.z, p1.w};
    float acc = 0.f;
#pragma unroll
    for (int e = 0; e < 8; e++)
        acc += pe[e] * __bfloat162float(h3[(size_t)e * B_ * M_OUT + t]);
    float x = acc * inv;
    out[t] = 1.f / (1.f + __expf(-x));
}

// ---------------- host launcher ----------------
extern "C" void kernel_launch(void* const* d_in, const int* in_sizes, int n_in,
                              void* d_out, int out_size) {
    const float* motions = (const float*)d_in[0];
    const float* z       = (const float*)d_in[1];
    const float* gw1     = (const float*)d_in[2];
    const float* gb1     = (const float*)d_in[3];
    const float* gw2     = (const float*)d_in[4];
    const float* gb2     = (const float*)d_in[5];
    const float* gw3     = (const float*)d_in[6];
    const float* gb3     = (const float*)d_in[7];
    const float* W1      = (const float*)d_in[8];
    const float* b1      = (const float*)d_in[9];
    const float* W2      = (const float*)d_in[10];
    const float* b2      = (const float*)d_in[11];
    const float* W3      = (const float*)d_in[12];
    const float* b3      = (const float*)d_in[13];
    float* out = (float*)d_out;

    unsigned char* sc = nullptr;
    cudaGetSymbolAddress((void**)&sc, g_scratch);
    __nv_bfloat16* xpad = (__nv_bfloat16*)(sc + OFF_XPAD);
    __nv_bfloat16* h1e  = (__nv_bfloat16*)(sc + OFF_H1);
    __nv_bfloat16* h2e  = (__nv_bfloat16*)(sc + OFF_H2);
    __nv_bfloat16* g1   = (__nv_bfloat16*)(sc + OFF_G1);
    __nv_bfloat16* g2   = (__nv_bfloat16*)(sc + OFF_G2);
    __nv_bfloat16* h3   = (__nv_bfloat16*)(sc + OFF_H3);
    float* para = (float*)(sc + OFF_PARA);
    float* part = (float*)(sc + OFF_PART);
    float* inv  = (float*)(sc + OFF_INV);
    __nv_bfloat16* gw1t = (__nv_bfloat16*)(sc + OFF_GW1T);
    __nv_bfloat16* gw2t = (__nv_bfloat16*)(sc + OFF_GW2T);
    __nv_bfloat16* W1t  = (__nv_bfloat16*)(sc + OFF_W1T);
    __nv_bfloat16* W2t  = (__nv_bfloat16*)(sc + OFF_W2T);
    __nv_bfloat16* W3t  = (__nv_bfloat16*)(sc + OFF_W3T);

    cudaFuncSetAttribute(gemm_bias_elu, cudaFuncAttributeMaxDynamicSharedMemorySize, SMEM_BYTES);

    prep_kernel<<<(B_ * (KX + 128)) / 256, 256>>>(motions, z, xpad, h1e, h2e);
    wconv_kernel<<<(WC_TOT + 255) / 256, 256>>>(gw1, gw2, W1, W2, W3, gw1t, gw2t, W1t, W2t, W3t);

    dim3 g4(B_ / 128, 4), gN1(B_ / 128, 1);
    // gate MLP
    gemm_bias_elu<<<g4, 256, SMEM_BYTES>>>(xpad, KX, gw1t, KX, gb1, g1, H, KX / 64);
    gemm_bias_elu<<<g4, 256, SMEM_BYTES>>>(g1, H, gw2t, H, gb2, g2, H, H / 64);
    gate3_kernel<<<B_ / 8, 256>>>(g2, gw3, gb3, para, part);
    reduce_norm_kernel<<<1, 256>>>(part, inv);

    // experts (sequential so intermediates stay L2-resident)
    for (int e = 0; e < NE; e++) {
        gemm_bias_elu<<<g4, 256, SMEM_BYTES>>>(xpad, KX, W1t + (size_t)e * H * KX, KX,
                                               b1 + (size_t)e * H, h1e, KH, KX / 64);
        gemm_bias_elu<<<g4, 256, SMEM_BYTES>>>(h1e, KH, W2t + (size_t)e * H * KH, KH,
                                               b2 + (size_t)e * H, h2e, KH, KH / 64);
        gemm_bias_elu<<<gN1, 256, SMEM_BYTES>>>(h2e, KH, W3t + (size_t)e * M_OUT * KH, KH,
                                                b3 + (size_t)e * M_OUT,
                                                h3 + (size_t)e * B_ * M_OUT, M_OUT, KH / 64);
    }

    combine_kernel<<<(B_ * M_OUT) / 256, 256>>>(para, h3, inv, out);
}

// round 3
// speedup vs baseline: 1.3643x; 1.3643x over previous
#include <cuda_runtime.h>
#include <cuda_bf16.h>
#include <stdint.h>

// ---------------- problem constants ----------------
static constexpr int B_    = 16384;
static constexpr int KX    = 320;   // padded input K (288 -> 320)
static constexpr int KH    = 576;   // padded hidden K (512 + 32 z + 32 pad)
static constexpr int H     = 512;
static constexpr int M_OUT = 128;
static constexpr int NE    = 8;

// ---------------- scratch layout (single __device__ array) ----------------
static constexpr size_t OFF_XPAD = 0;
static constexpr size_t SZ_XPAD  = (size_t)B_*KX*2;
static constexpr size_t OFF_H1   = OFF_XPAD + SZ_XPAD;
static constexpr size_t SZ_HEXT  = (size_t)NE*B_*KH*2;      // per-expert
static constexpr size_t OFF_H2   = OFF_H1 + SZ_HEXT;
static constexpr size_t OFF_G1   = OFF_H2 + SZ_HEXT;
static constexpr size_t SZ_G     = (size_t)B_*H*2;
static constexpr size_t OFF_G2   = OFF_G1 + SZ_G;
static constexpr size_t OFF_H3   = OFF_G2 + SZ_G;
static constexpr size_t SZ_H3    = (size_t)NE*B_*M_OUT*2;
static constexpr size_t OFF_PARA = OFF_H3 + SZ_H3;
static constexpr size_t SZ_PARA  = (size_t)B_*NE*4;
static constexpr size_t OFF_PART = OFF_PARA + SZ_PARA;
static constexpr size_t SZ_PART  = 2048*4;
static constexpr size_t OFF_INV  = OFF_PART + SZ_PART;
static constexpr size_t SZ_INV   = 256;
static constexpr size_t OFF_GW1T = OFF_INV + SZ_INV;
static constexpr size_t SZ_GW1T  = (size_t)H*KX*2;
static constexpr size_t OFF_GW2T = OFF_GW1T + SZ_GW1T;
static constexpr size_t SZ_GW2T  = (size_t)H*H*2;
static constexpr size_t OFF_W1T  = OFF_GW2T + SZ_GW2T;
static constexpr size_t SZ_W1T   = (size_t)NE*H*KX*2;
static constexpr size_t OFF_W2T  = OFF_W1T + SZ_W1T;
static constexpr size_t SZ_W2T   = (size_t)NE*H*KH*2;
static constexpr size_t OFF_W3T  = OFF_W2T + SZ_W2T;
static constexpr size_t SZ_W3T   = (size_t)NE*M_OUT*KH*2;
static constexpr size_t SCRATCH_TOTAL = OFF_W3T + SZ_W3T;

__device__ __align__(1024) unsigned char g_scratch[SCRATCH_TOTAL];

// ---------------- helpers ----------------
__device__ __forceinline__ uint32_t smem_u32(const void* p) {
    return (uint32_t)__cvta_generic_to_shared(p);
}
__device__ __forceinline__ uint32_t swz128(uint32_t off) {
    return off ^ ((off >> 3) & 0x70);
}
__device__ __forceinline__ void cp16(uint32_t dst, const void* src) {
    asm volatile("cp.async.cg.shared.global [%0], [%1], 16;\n" :: "r"(dst), "l"(src) : "memory");
}
__device__ __forceinline__ void ldsm_x4(uint32_t& r0, uint32_t& r1, uint32_t& r2, uint32_t& r3,
                                        uint32_t addr) {
    asm volatile("ldmatrix.sync.aligned.m8n8.x4.shared.b16 {%0,%1,%2,%3}, [%4];"
                 : "=r"(r0), "=r"(r1), "=r"(r2), "=r"(r3) : "r"(addr));
}
__device__ __forceinline__ void mma16816(float* c, uint32_t a0, uint32_t a1, uint32_t a2, uint32_t a3,
                                         uint32_t b0, uint32_t b1) {
    asm volatile(
        "mma.sync.aligned.m16n8k16.row.col.f32.bf16.bf16.f32 "
        "{%0,%1,%2,%3}, {%4,%5,%6,%7}, {%8,%9}, {%0,%1,%2,%3};"
        : "+f"(c[0]), "+f"(c[1]), "+f"(c[2]), "+f"(c[3])
        : "r"(a0), "r"(a1), "r"(a2), "r"(a3), "r"(b0), "r"(b1));
}

// ---------------- prep kernel ----------------
// Fills xpad[B,KX] and the z-columns [512:576) of all 16 per-expert hidden buffers.
__global__ void prep_kernel(const float* __restrict__ motions, const float* __restrict__ z,
                            __nv_bfloat16* __restrict__ xpad,
                            __nv_bfloat16* __restrict__ h1e, __nv_bfloat16* __restrict__ h2e) {
    int idx = blockIdx.x * 256 + threadIdx.x;
    const int XT = B_ * KX;
    const int ZT = B_ * 64;
    if (idx < XT) {
        int row = idx / KX, c = idx % KX;
        float v = 0.f;
        if (c < 256)      v = motions[(size_t)row * 256 + c];
        else if (c < 288) v = z[(size_t)row * 32 + (c - 256)];
        xpad[idx] = __float2bfloat16(v);
    } else if (idx < XT + ZT) {
        int j = idx - XT;
        int row = j / 64, c = j % 64;
        __nv_bfloat16 v = __float2bfloat16(c < 32 ? z[(size_t)row * 32 + c] : 0.f);
        size_t base = (size_t)row * KH + 512 + c;
#pragma unroll
        for (int e = 0; e < NE; e++) {
            h1e[(size_t)e * B_ * KH + base] = v;
            h2e[(size_t)e * B_ * KH + base] = v;
        }
    }
}

// ---------------- weight convert/transpose/pad kernel ----------------
static constexpr int WC_C0 = H * KX;
static constexpr int WC_C1 = H * H;
static constexpr int WC_C2 = NE * H * KX;
static constexpr int WC_C3 = NE * H * KH;
static constexpr int WC_C4 = NE * M_OUT * KH;
static constexpr int WC_TOT = WC_C0 + WC_C1 + WC_C2 + WC_C3 + WC_C4;

__global__ void wconv_kernel(const float* __restrict__ gw1, const float* __restrict__ gw2,
                             const float* __restrict__ W1, const float* __restrict__ W2,
                             const float* __restrict__ W3,
                             __nv_bfloat16* __restrict__ gw1t, __nv_bfloat16* __restrict__ gw2t,
                             __nv_bfloat16* __restrict__ W1t, __nv_bfloat16* __restrict__ W2t,
                             __nv_bfloat16* __restrict__ W3t) {
    int idx = blockIdx.x * 256 + threadIdx.x;
    if (idx < WC_C0) {
        int n = idx / KX, k = idx % KX;
        gw1t[idx] = __float2bfloat16(k < 288 ? gw1[(size_t)k * H + n] : 0.f);
        return;
    }
    idx -= WC_C0;
    if (idx < WC_C1) {
        int n = idx / H, k = idx % H;
        gw2t[idx] = __float2bfloat16(gw2[(size_t)k * H + n]);
        return;
    }
    idx -= WC_C1;
    if (idx < WC_C2) {
        int e = idx / (H * KX); int r = idx % (H * KX); int n = r / KX, k = r % KX;
        W1t[idx] = __float2bfloat16(k < 288 ? W1[((size_t)e * 288 + k) * H + n] : 0.f);
        return;
    }
    idx -= WC_C2;
    if (idx < WC_C3) {
        int e = idx / (H * KH); int r = idx % (H * KH); int n = r / KH, k = r % KH;
        W2t[idx] = __float2bfloat16(k < 544 ? W2[((size_t)e * 544 + k) * H + n] : 0.f);
        return;
    }
    idx -= WC_C3;
    if (idx < WC_C4) {
        int e = idx / (M_OUT * KH); int r = idx % (M_OUT * KH); int n = r / KH, k = r % KH;
        W3t[idx] = __float2bfloat16(k < 544 ? W3[((size_t)e * 544 + k) * M_OUT + n] : 0.f);
    }
}

// ---------------- HMMA GEMM: C[m,n] = elu(sum_k A[m,k]*Bt[n,k] + bias[n]) -> bf16 ----------------
// CTA: 256 threads, tile 128(M) x 128(N), K-chunks of 64, 2-stage cp.async, 2 CTAs/SM.
// Warp layout: 2 (M) x 4 (N) warps; warp tile 64x32 = 4x4 m16n8k16 frags.
// blockIdx.z selects the expert via element strides (0 strides for the gate GEMMs).
static constexpr int STAGE_BYTES = 16384 + 16384;              // A tile + B tile (128 x 128B each)
static constexpr int SMEM_BYTES  = 1024 + 2 * STAGE_BYTES;     // bias + 2 stages = 66560

__global__ __launch_bounds__(256, 2)
void gemm_bias_elu(const __nv_bfloat16* __restrict__ A, int lda, size_t a_es,
                   const __nv_bfloat16* __restrict__ Bw, int ldb, size_t b_es,
                   const float* __restrict__ bias, int bias_es,
                   __nv_bfloat16* __restrict__ C, int ldc, size_t c_es, int kchunks) {
    extern __shared__ unsigned char smem[];
    float* sbias = (float*)smem;
    unsigned char* tiles = smem + 1024;
    const uint32_t tiles_u = smem_u32(tiles);
    const int tid = threadIdx.x;
    const int e  = blockIdx.z;
    const int m0 = blockIdx.x * 128, n0 = blockIdx.y * 128;
    A    += (size_t)e * a_es;
    Bw   += (size_t)e * b_es;
    bias += (size_t)e * bias_es;
    C    += (size_t)e * c_es;

    if (tid < 128) sbias[tid] = bias[n0 + tid];

    // --- loader precompute: 4 x 16B per tile (A and B) per thread ---
    int lrow[4], lseg[4];
#pragma unroll
    for (int i = 0; i < 4; i++) {
        int id = tid * 4 + i;          // 0..1023
        lrow[i] = id >> 3;             // 0..127
        lseg[i] = (id & 7) * 16;       // byte seg within 128B row
    }
    const char* agbase = (const char*)(A + (size_t)m0 * lda);
    const char* bgbase = (const char*)(Bw + (size_t)n0 * ldb);
    uint32_t sdst[4];
#pragma unroll
    for (int i = 0; i < 4; i++) sdst[i] = swz128((uint32_t)(lrow[i] * 128 + lseg[i]));

    auto load_stage = [&](int s, int buf) {
        uint32_t ab = tiles_u + buf * STAGE_BYTES;
        uint32_t bb = ab + 16384;
        const char* asrc = agbase + (size_t)s * 128;   // 64 bf16 = 128B along K
        const char* bsrc = bgbase + (size_t)s * 128;
#pragma unroll
        for (int i = 0; i < 4; i++) {
            cp16(ab + sdst[i], asrc + (size_t)lrow[i] * (lda * 2) + lseg[i]);
            cp16(bb + sdst[i], bsrc + (size_t)lrow[i] * (ldb * 2) + lseg[i]);
        }
        asm volatile("cp.async.commit_group;" ::: "memory");
    };

    load_stage(0, 0);

    const int lane = tid & 31, w = tid >> 5;
    const int wm = (w >> 2) * 64;       // warp M offset (0 or 64)
    const int wn = (w & 3) * 32;        // warp N offset (0,32,64,96)
    const int arow = lane & 15, ahalf = (lane >> 4) * 16;

    float acc[4][4][4];
#pragma unroll
    for (int mf = 0; mf < 4; mf++)
#pragma unroll
        for (int nf = 0; nf < 4; nf++)
#pragma unroll
            for (int i = 0; i < 4; i++) acc[mf][nf][i] = 0.f;

    for (int s = 0; s < kchunks; s++) {
        if (s + 1 < kchunks) load_stage(s + 1, (s + 1) & 1);
        else asm volatile("cp.async.commit_group;" ::: "memory"); // keep group count aligned
        asm volatile("cp.async.wait_group 1;" ::: "memory");
        __syncthreads();

        uint32_t abase = tiles_u + (s & 1) * STAGE_BYTES;
        uint32_t bbase = abase + 16384;
#pragma unroll
        for (int kk = 0; kk < 4; kk++) {
            uint32_t af[4][4];
#pragma unroll
            for (int mf = 0; mf < 4; mf++) {
                uint32_t off = (uint32_t)((wm + mf * 16 + arow) * 128 + kk * 32 + ahalf);
                ldsm_x4(af[mf][0], af[mf][1], af[mf][2], af[mf][3], abase + swz128(off));
            }
            uint32_t bf[2][4];
#pragma unroll
            for (int p = 0; p < 2; p++) {
                uint32_t off = (uint32_t)((wn + p * 16 + arow) * 128 + kk * 32 + ahalf);
                ldsm_x4(bf[p][0], bf[p][1], bf[p][2], bf[p][3], bbase + swz128(off));
            }
#pragma unroll
            for (int mf = 0; mf < 4; mf++) {
#pragma unroll
                for (int p = 0; p < 2; p++) {
                    mma16816(acc[mf][2 * p],     af[mf][0], af[mf][1], af[mf][2], af[mf][3],
                             bf[p][0], bf[p][2]);
                    mma16816(acc[mf][2 * p + 1], af[mf][0], af[mf][1], af[mf][2], af[mf][3],
                             bf[p][1], bf[p][3]);
                }
            }
        }
        __syncthreads();
    }

    // ---- epilogue: bias + ELU + bf16 store ----
    const int cg = lane >> 2;            // 0..7 (row group)
    const int cc = (lane & 3) * 2;       // col pair
#pragma unroll
    for (int mf = 0; mf < 4; mf++) {
        int r0 = m0 + wm + mf * 16 + cg;
        int r1 = r0 + 8;
#pragma unroll
        for (int nf = 0; nf < 4; nf++) {
            int col = wn + nf * 8 + cc;
            float b0 = sbias[col], b1 = sbias[col + 1];
            float v0 = acc[mf][nf][0] + b0, v1 = acc[mf][nf][1] + b1;
            float v2 = acc[mf][nf][2] + b0, v3 = acc[mf][nf][3] + b1;
            v0 = v0 > 0.f ? v0 : (__expf(v0) - 1.f);
            v1 = v1 > 0.f ? v1 : (__expf(v1) - 1.f);
            v2 = v2 > 0.f ? v2 : (__expf(v2) - 1.f);
            v3 = v3 > 0.f ? v3 : (__expf(v3) - 1.f);
            *(__nv_bfloat162*)(C + (size_t)r0 * ldc + n0 + col) = __floats2bfloat162_rn(v0, v1);
            *(__nv_bfloat162*)(C + (size_t)r1 * ldc + n0 + col) = __floats2bfloat162_rn(v2, v3);
        }
    }
}

// ---------------- gate layer 3 (N=8) + deterministic partial norm ----------------
__global__ void gate3_kernel(const __nv_bfloat16* __restrict__ g2,
                             const float* __restrict__ gw3, const float* __restrict__ gb3,
                             float* __restrict__ para, float* __restrict__ partial) {
    __shared__ float sw[8 * 512];
    __shared__ float wsum[8];
    int tid = threadIdx.x;
    for (int i = tid; i < 4096; i += 256) { int k = i / 8, e = i % 8; sw[e * 512 + k] = gw3[k * 8 + e]; }
    __syncthreads();
    int warp = tid / 32, lane = tid % 32;
    int row = blockIdx.x * 8 + warp;
    float acc[8];
#pragma unroll
    for (int e = 0; e < 8; e++) acc[e] = 0.f;
    const __nv_bfloat162* gr = (const __nv_bfloat162*)(g2 + (size_t)row * 512);
#pragma unroll
    for (int i = 0; i < 8; i++) {
        __nv_bfloat162 p = gr[i * 32 + lane];
        float a0 = __bfloat162float(p.x), a1 = __bfloat162float(p.y);
        int k0 = i * 64 + lane * 2;
#pragma unroll
        for (int e = 0; e < 8; e++) acc[e] += a0 * sw[e * 512 + k0] + a1 * sw[e * 512 + k0 + 1];
    }
#pragma unroll
    for (int off = 16; off; off >>= 1)
#pragma unroll
        for (int e = 0; e < 8; e++) acc[e] += __shfl_down_sync(0xFFFFFFFFu, acc[e], off);
    if (lane == 0) {
        float ss = 0.f;
#pragma unroll
        for (int e = 0; e < 8; e++) {
            float v = acc[e] + gb3[e];
            v = v > 0.f ? v : (__expf(v) - 1.f);
            para[(size_t)row * 8 + e] = v;
            ss += v * v;
        }
        wsum[warp] = ss;
    }
    __syncthreads();
    if (tid == 0) {
        float s = 0.f;
        for (int w = 0; w < 8; w++) s += wsum[w];
        partial[blockIdx.x] = s;
    }
}

__global__ void reduce_norm_kernel(const float* __restrict__ partial, float* __restrict__ invnorm) {
    __shared__ float s[256];
    int tid = threadIdx.x;
    float v = 0.f;
    for (int k = 0; k < 8; k++) v += partial[tid + k * 256];
    s[tid] = v;
    __syncthreads();
    for (int off = 128; off; off >>= 1) {
        if (tid < off) s[tid] += s[tid + off];
        __syncthreads();
    }
    if (tid == 0) *invnorm = rsqrtf(s[0]);
}

// ---------------- combine: out = sigmoid(invnorm * sum_e para[b,e]*h3[e,b,m]) ----------------
__global__ void combine_kernel(const float* __restrict__ para, const __nv_bfloat16* __restrict__ h3,
                               const float* __restrict__ invnorm, float* __restrict__ out) {
    int t = blockIdx.x * 256 + threadIdx.x;   // t < B_*128
    int b = t >> 7;
    float inv = *invnorm;
    float4 p0 = ((const float4*)para)[b * 2];
    float4 p1 = ((const float4*)para)[b * 2 + 1];
    float pe[8] = {p0.x, p0.y, p0.z, p0.w, p1.x, p1.y, p1.z, p1.w};
    float acc = 0.f;
#pragma unroll
    for (int e = 0; e < 8; e++)
        acc += pe[e] * __bfloat162float(h3[(size_t)e * B_ * M_OUT + t]);
    float x = acc * inv;
    out[t] = 1.f / (1.f + __expf(-x));
}

// ---------------- host launcher ----------------
extern "C" void kernel_launch(void* const* d_in, const int* in_sizes, int n_in,
                              void* d_out, int out_size) {
    const float* motions = (const float*)d_in[0];
    const float* z       = (const float*)d_in[1];
    const float* gw1     = (const float*)d_in[2];
    const float* gb1     = (const float*)d_in[3];
    const float* gw2     = (const float*)d_in[4];
    const float* gb2     = (const float*)d_in[5];
    const float* gw3     = (const float*)d_in[6];
    const float* gb3     = (const float*)d_in[7];
    const float* W1      = (const float*)d_in[8];
    const float* b1      = (const float*)d_in[9];
    const float* W2      = (const float*)d_in[10];
    const float* b2      = (const float*)d_in[11];
    const float* W3      = (const float*)d_in[12];
    const float* b3      = (const float*)d_in[13];
    float* out = (float*)d_out;

    unsigned char* sc = nullptr;
    cudaGetSymbolAddress((void**)&sc, g_scratch);
    __nv_bfloat16* xpad = (__nv_bfloat16*)(sc + OFF_XPAD);
    __nv_bfloat16* h1e  = (__nv_bfloat16*)(sc + OFF_H1);
    __nv_bfloat16* h2e  = (__nv_bfloat16*)(sc + OFF_H2);
    __nv_bfloat16* g1   = (__nv_bfloat16*)(sc + OFF_G1);
    __nv_bfloat16* g2   = (__nv_bfloat16*)(sc + OFF_G2);
    __nv_bfloat16* h3   = (__nv_bfloat16*)(sc + OFF_H3);
    float* para = (float*)(sc + OFF_PARA);
    float* part = (float*)(sc + OFF_PART);
    float* inv  = (float*)(sc + OFF_INV);
    __nv_bfloat16* gw1t = (__nv_bfloat16*)(sc + OFF_GW1T);
    __nv_bfloat16* gw2t = (__nv_bfloat16*)(sc + OFF_GW2T);
    __nv_bfloat16* W1t  = (__nv_bfloat16*)(sc + OFF_W1T);
    __nv_bfloat16* W2t  = (__nv_bfloat16*)(sc + OFF_W2T);
    __nv_bfloat16* W3t  = (__nv_bfloat16*)(sc + OFF_W3T);

    cudaFuncSetAttribute(gemm_bias_elu, cudaFuncAttributeMaxDynamicSharedMemorySize, SMEM_BYTES);

    const int PREP_T = B_ * (KX + 64);
    prep_kernel<<<(PREP_T + 255) / 256, 256>>>(motions, z, xpad, h1e, h2e);
    wconv_kernel<<<(WC_TOT + 255) / 256, 256>>>(gw1, gw2, W1, W2, W3, gw1t, gw2t, W1t, W2t, W3t);

    dim3 gGate(B_ / 128, 4, 1);
    dim3 gE12(B_ / 128, 4, NE);
    dim3 gE3(B_ / 128, 1, NE);

    // gate MLP
    gemm_bias_elu<<<gGate, 256, SMEM_BYTES>>>(xpad, KX, 0, gw1t, KX, 0, gb1, 0,
                                              g1, H, 0, KX / 64);
    gemm_bias_elu<<<gGate, 256, SMEM_BYTES>>>(g1, H, 0, gw2t, H, 0, gb2, 0,
                                              g2, H, 0, H / 64);
    gate3_kernel<<<B_ / 8, 256>>>(g2, gw3, gb3, para, part);
    reduce_norm_kernel<<<1, 256>>>(part, inv);

    // experts: one batched launch per layer (blockIdx.z = expert)
    gemm_bias_elu<<<gE12, 256, SMEM_BYTES>>>(xpad, KX, 0,
                                             W1t, KX, (size_t)H * KX,
                                             b1, H,
                                             h1e, KH, (size_t)B_ * KH, KX / 64);
    gemm_bias_elu<<<gE12, 256, SMEM_BYTES>>>(h1e, KH, (size_t)B_ * KH,
                                             W2t, KH, (size_t)H * KH,
                                             b2, H,
                                             h2e, KH, (size_t)B_ * KH, KH / 64);
    gemm_bias_elu<<<gE3, 256, SMEM_BYTES>>>(h2e, KH, (size_t)B_ * KH,
                                            W3t, KH, (size_t)M_OUT * KH,
                                            b3, M_OUT,
                                            h3, M_OUT, (size_t)B_ * M_OUT, KH / 64);

    combine_kernel<<<(B_ * M_OUT) / 256, 256>>>(para, h3, inv, out);
}

// round 4
// speedup vs baseline: 1.3918x; 1.0202x over previous
#include <cuda_runtime.h>
#include <cuda_bf16.h>
#include <stdint.h>

// ---------------- problem constants ----------------
static constexpr int B_    = 16384;
static constexpr int KX    = 320;   // padded input K (288 -> 320)
static constexpr int KH    = 576;   // padded hidden K (512 + 32 z + 32 pad)
static constexpr int H     = 512;
static constexpr int M_OUT = 128;
static constexpr int NE    = 8;

// ---------------- scratch layout (single __device__ array) ----------------
static constexpr size_t OFF_XPAD = 0;
static constexpr size_t SZ_XPAD  = (size_t)B_*KX*2;
static constexpr size_t OFF_H1   = OFF_XPAD + SZ_XPAD;
static constexpr size_t SZ_HEXT  = (size_t)NE*B_*KH*2;      // per-expert
static constexpr size_t OFF_H2   = OFF_H1 + SZ_HEXT;
static constexpr size_t OFF_G1   = OFF_H2 + SZ_HEXT;
static constexpr size_t SZ_G     = (size_t)B_*H*2;
static constexpr size_t OFF_G2   = OFF_G1 + SZ_G;
static constexpr size_t OFF_H3   = OFF_G2 + SZ_G;
static constexpr size_t SZ_H3    = (size_t)NE*B_*M_OUT*2;
static constexpr size_t OFF_PARA = OFF_H3 + SZ_H3;
static constexpr size_t SZ_PARA  = (size_t)B_*NE*4;
static constexpr size_t OFF_PART = OFF_PARA + SZ_PARA;
static constexpr size_t SZ_PART  = 2048*4;
static constexpr size_t OFF_INV  = OFF_PART + SZ_PART;
static constexpr size_t SZ_INV   = 256;
static constexpr size_t OFF_GW1T = OFF_INV + SZ_INV;
static constexpr size_t SZ_GW1T  = (size_t)H*KX*2;
static constexpr size_t OFF_GW2T = OFF_GW1T + SZ_GW1T;
static constexpr size_t SZ_GW2T  = (size_t)H*H*2;
static constexpr size_t OFF_W1T  = OFF_GW2T + SZ_GW2T;
static constexpr size_t SZ_W1T   = (size_t)NE*H*KX*2;
static constexpr size_t OFF_W2T  = OFF_W1T + SZ_W1T;
static constexpr size_t SZ_W2T   = (size_t)NE*H*KH*2;
static constexpr size_t OFF_W3T  = OFF_W2T + SZ_W2T;
static constexpr size_t SZ_W3T   = (size_t)NE*M_OUT*KH*2;
static constexpr size_t SCRATCH_TOTAL = OFF_W3T + SZ_W3T;

__device__ __align__(1024) unsigned char g_scratch[SCRATCH_TOTAL];

// ---------------- helpers ----------------
__device__ __forceinline__ uint32_t smem_u32(const void* p) {
    return (uint32_t)__cvta_generic_to_shared(p);
}
__device__ __forceinline__ uint32_t swz128(uint32_t off) {
    return off ^ ((off >> 3) & 0x70);
}
__device__ __forceinline__ void cp16(uint32_t dst, const void* src) {
    asm volatile("cp.async.cg.shared.global [%0], [%1], 16;\n" :: "r"(dst), "l"(src) : "memory");
}
__device__ __forceinline__ void ldsm_x4(uint32_t& r0, uint32_t& r1, uint32_t& r2, uint32_t& r3,
                                        uint32_t addr) {
    asm volatile("ldmatrix.sync.aligned.m8n8.x4.shared.b16 {%0,%1,%2,%3}, [%4];"
                 : "=r"(r0), "=r"(r1), "=r"(r2), "=r"(r3) : "r"(addr));
}
__device__ __forceinline__ void mma16816(float* c, uint32_t a0, uint32_t a1, uint32_t a2, uint32_t a3,
                                         uint32_t b0, uint32_t b1) {
    asm volatile(
        "mma.sync.aligned.m16n8k16.row.col.f32.bf16.bf16.f32 "
        "{%0,%1,%2,%3}, {%4,%5,%6,%7}, {%8,%9}, {%0,%1,%2,%3};"
        : "+f"(c[0]), "+f"(c[1]), "+f"(c[2]), "+f"(c[3])
        : "r"(a0), "r"(a1), "r"(a2), "r"(a3), "r"(b0), "r"(b1));
}

// ---------------- prep kernel ----------------
__global__ void prep_kernel(const float* __restrict__ motions, const float* __restrict__ z,
                            __nv_bfloat16* __restrict__ xpad,
                            __nv_bfloat16* __restrict__ h1e, __nv_bfloat16* __restrict__ h2e) {
    int idx = blockIdx.x * 256 + threadIdx.x;
    const int XT = B_ * KX;
    const int ZT = B_ * 64;
    if (idx < XT) {
        int row = idx / KX, c = idx % KX;
        float v = 0.f;
        if (c < 256)      v = motions[(size_t)row * 256 + c];
        else if (c < 288) v = z[(size_t)row * 32 + (c - 256)];
        xpad[idx] = __float2bfloat16(v);
    } else if (idx < XT + ZT) {
        int j = idx - XT;
        int row = j / 64, c = j % 64;
        __nv_bfloat16 v = __float2bfloat16(c < 32 ? z[(size_t)row * 32 + c] : 0.f);
        size_t base = (size_t)row * KH + 512 + c;
#pragma unroll
        for (int e = 0; e < NE; e++) {
            h1e[(size_t)e * B_ * KH + base] = v;
            h2e[(size_t)e * B_ * KH + base] = v;
        }
    }
}

// ---------------- weight convert/transpose/pad kernel ----------------
static constexpr int WC_C0 = H * KX;
static constexpr int WC_C1 = H * H;
static constexpr int WC_C2 = NE * H * KX;
static constexpr int WC_C3 = NE * H * KH;
static constexpr int WC_C4 = NE * M_OUT * KH;
static constexpr int WC_TOT = WC_C0 + WC_C1 + WC_C2 + WC_C3 + WC_C4;

__global__ void wconv_kernel(const float* __restrict__ gw1, const float* __restrict__ gw2,
                             const float* __restrict__ W1, const float* __restrict__ W2,
                             const float* __restrict__ W3,
                             __nv_bfloat16* __restrict__ gw1t, __nv_bfloat16* __restrict__ gw2t,
                             __nv_bfloat16* __restrict__ W1t, __nv_bfloat16* __restrict__ W2t,
                             __nv_bfloat16* __restrict__ W3t) {
    int idx = blockIdx.x * 256 + threadIdx.x;
    if (idx < WC_C0) {
        int n = idx / KX, k = idx % KX;
        gw1t[idx] = __float2bfloat16(k < 288 ? gw1[(size_t)k * H + n] : 0.f);
        return;
    }
    idx -= WC_C0;
    if (idx < WC_C1) {
        int n = idx / H, k = idx % H;
        gw2t[idx] = __float2bfloat16(gw2[(size_t)k * H + n]);
        return;
    }
    idx -= WC_C1;
    if (idx < WC_C2) {
        int e = idx / (H * KX); int r = idx % (H * KX); int n = r / KX, k = r % KX;
        W1t[idx] = __float2bfloat16(k < 288 ? W1[((size_t)e * 288 + k) * H + n] : 0.f);
        return;
    }
    idx -= WC_C2;
    if (idx < WC_C3) {
        int e = idx / (H * KH); int r = idx % (H * KH); int n = r / KH, k = r % KH;
        W2t[idx] = __float2bfloat16(k < 544 ? W2[((size_t)e * 544 + k) * H + n] : 0.f);
        return;
    }
    idx -= WC_C3;
    if (idx < WC_C4) {
        int e = idx / (M_OUT * KH); int r = idx % (M_OUT * KH); int n = r / KH, k = r % KH;
        W3t[idx] = __float2bfloat16(k < 544 ? W3[((size_t)e * 544 + k) * M_OUT + n] : 0.f);
    }
}

// ---------------- HMMA GEMM: C[m,n] = elu(sum_k A[m,k]*Bt[n,k] + bias[n]) -> bf16 ----------------
// CTA: 256 threads, tile 128(M) x 128(N), K-chunks of 64, 3-stage cp.async ring,
// ONE __syncthreads per chunk, 2 CTAs/SM.
// Warp layout: 2 (M) x 4 (N) warps; warp tile 64x32 = 4x4 m16n8k16 frags.
static constexpr int STAGE_BYTES = 16384 + 16384;              // A tile + B tile (128 x 128B each)
static constexpr int NSTAGE     = 3;
static constexpr int SMEM_BYTES  = 1024 + NSTAGE * STAGE_BYTES; // 99328

__global__ __launch_bounds__(256, 2)
void gemm_bias_elu(const __nv_bfloat16* __restrict__ A, int lda, size_t a_es,
                   const __nv_bfloat16* __restrict__ Bw, int ldb, size_t b_es,
                   const float* __restrict__ bias, int bias_es,
                   __nv_bfloat16* __restrict__ C, int ldc, size_t c_es, int kchunks) {
    extern __shared__ unsigned char smem[];
    float* sbias = (float*)smem;
    unsigned char* tiles = smem + 1024;
    const uint32_t tiles_u = smem_u32(tiles);
    const int tid = threadIdx.x;
    const int e  = blockIdx.z;
    const int m0 = blockIdx.x * 128, n0 = blockIdx.y * 128;
    A    += (size_t)e * a_es;
    Bw   += (size_t)e * b_es;
    bias += (size_t)e * bias_es;
    C    += (size_t)e * c_es;

    if (tid < 128) sbias[tid] = bias[n0 + tid];

    // --- loader precompute: 4 x 16B per tile (A and B) per thread ---
    int lrow[4], lseg[4];
#pragma unroll
    for (int i = 0; i < 4; i++) {
        int id = tid * 4 + i;          // 0..1023
        lrow[i] = id >> 3;             // 0..127
        lseg[i] = (id & 7) * 16;       // byte seg within 128B row
    }
    const char* agbase = (const char*)(A + (size_t)m0 * lda);
    const char* bgbase = (const char*)(Bw + (size_t)n0 * ldb);
    uint32_t sdst[4];
#pragma unroll
    for (int i = 0; i < 4; i++) sdst[i] = swz128((uint32_t)(lrow[i] * 128 + lseg[i]));

    auto load_stage = [&](int s, int buf) {
        uint32_t ab = tiles_u + buf * STAGE_BYTES;
        uint32_t bb = ab + 16384;
        const char* asrc = agbase + (size_t)s * 128;   // 64 bf16 = 128B along K
        const char* bsrc = bgbase + (size_t)s * 128;
#pragma unroll
        for (int i = 0; i < 4; i++) {
            cp16(ab + sdst[i], asrc + (size_t)lrow[i] * (lda * 2) + lseg[i]);
            cp16(bb + sdst[i], bsrc + (size_t)lrow[i] * (ldb * 2) + lseg[i]);
        }
        asm volatile("cp.async.commit_group;" ::: "memory");
    };

    // prologue: stages 0 and 1 in flight
    load_stage(0, 0);
    load_stage(1, 1);

    const int lane = tid & 31, w = tid >> 5;
    const int wm = (w >> 2) * 64;       // warp M offset (0 or 64)
    const int wn = (w & 3) * 32;        // warp N offset (0,32,64,96)
    const int arow = lane & 15, ahalf = (lane >> 4) * 16;

    float acc[4][4][4];
#pragma unroll
    for (int mf = 0; mf < 4; mf++)
#pragma unroll
        for (int nf = 0; nf < 4; nf++)
#pragma unroll
            for (int i = 0; i < 4; i++) acc[mf][nf][i] = 0.f;

    int buf = 0;                 // s % 3
    int nbuf = 2;                // (s+2) % 3
    for (int s = 0; s < kchunks; s++) {
        // wait until load s complete (groups outstanding <= 1)
        asm volatile("cp.async.wait_group 1;" ::: "memory");
        __syncthreads();   // all threads' stage-s data visible; all reads of buffer nbuf (iter s-1) done
        if (s + 2 < kchunks) load_stage(s + 2, nbuf);
        else asm volatile("cp.async.commit_group;" ::: "memory"); // keep group count aligned

        uint32_t abase = tiles_u + buf * STAGE_BYTES;
        uint32_t bbase = abase + 16384;
#pragma unroll
        for (int kk = 0; kk < 4; kk++) {
            uint32_t af[4][4];
#pragma unroll
            for (int mf = 0; mf < 4; mf++) {
                uint32_t off = (uint32_t)((wm + mf * 16 + arow) * 128 + kk * 32 + ahalf);
                ldsm_x4(af[mf][0], af[mf][1], af[mf][2], af[mf][3], abase + swz128(off));
            }
            uint32_t bf[2][4];
#pragma unroll
            for (int p = 0; p < 2; p++) {
                uint32_t off = (uint32_t)((wn + p * 16 + arow) * 128 + kk * 32 + ahalf);
                ldsm_x4(bf[p][0], bf[p][1], bf[p][2], bf[p][3], bbase + swz128(off));
            }
#pragma unroll
            for (int mf = 0; mf < 4; mf++) {
#pragma unroll
                for (int p = 0; p < 2; p++) {
                    mma16816(acc[mf][2 * p],     af[mf][0], af[mf][1], af[mf][2], af[mf][3],
                             bf[p][0], bf[p][2]);
                    mma16816(acc[mf][2 * p + 1], af[mf][0], af[mf][1], af[mf][2], af[mf][3],
                             bf[p][1], bf[p][3]);
                }
            }
        }
        buf = (buf == 2) ? 0 : buf + 1;
        nbuf = (nbuf == 2) ? 0 : nbuf + 1;
    }

    // ---- epilogue: bias + ELU + bf16 store ----
    const int cg = lane >> 2;            // 0..7 (row group)
    const int cc = (lane & 3) * 2;       // col pair
#pragma unroll
    for (int mf = 0; mf < 4; mf++) {
        int r0 = m0 + wm + mf * 16 + cg;
        int r1 = r0 + 8;
#pragma unroll
        for (int nf = 0; nf < 4; nf++) {
            int col = wn + nf * 8 + cc;
            float b0 = sbias[col], b1 = sbias[col + 1];
            float v0 = acc[mf][nf][0] + b0, v1 = acc[mf][nf][1] + b1;
            float v2 = acc[mf][nf][2] + b0, v3 = acc[mf][nf][3] + b1;
            v0 = v0 > 0.f ? v0 : (__expf(v0) - 1.f);
            v1 = v1 > 0.f ? v1 : (__expf(v1) - 1.f);
            v2 = v2 > 0.f ? v2 : (__expf(v2) - 1.f);
            v3 = v3 > 0.f ? v3 : (__expf(v3) - 1.f);
            *(__nv_bfloat162*)(C + (size_t)r0 * ldc + n0 + col) = __floats2bfloat162_rn(v0, v1);
            *(__nv_bfloat162*)(C + (size_t)r1 * ldc + n0 + col) = __floats2bfloat162_rn(v2, v3);
        }
    }
}

// ---------------- gate layer 3 (N=8) + deterministic partial norm ----------------
__global__ void gate3_kernel(const __nv_bfloat16* __restrict__ g2,
                             const float* __restrict__ gw3, const float* __restrict__ gb3,
                             float* __restrict__ para, float* __restrict__ partial) {
    __shared__ float sw[8 * 512];
    __shared__ float wsum[8];
    int tid = threadIdx.x;
    for (int i = tid; i < 4096; i += 256) { int k = i / 8, e = i % 8; sw[e * 512 + k] = gw3[k * 8 + e]; }
    __syncthreads();
    int warp = tid / 32, lane = tid % 32;
    int row = blockIdx.x * 8 + warp;
    float acc[8];
#pragma unroll
    for (int e = 0; e < 8; e++) acc[e] = 0.f;
    const __nv_bfloat162* gr = (const __nv_bfloat162*)(g2 + (size_t)row * 512);
#pragma unroll
    for (int i = 0; i < 8; i++) {
        __nv_bfloat162 p = gr[i * 32 + lane];
        float a0 = __bfloat162float(p.x), a1 = __bfloat162float(p.y);
        int k0 = i * 64 + lane * 2;
#pragma unroll
        for (int e = 0; e < 8; e++) acc[e] += a0 * sw[e * 512 + k0] + a1 * sw[e * 512 + k0 + 1];
    }
#pragma unroll
    for (int off = 16; off; off >>= 1)
#pragma unroll
        for (int e = 0; e < 8; e++) acc[e] += __shfl_down_sync(0xFFFFFFFFu, acc[e], off);
    if (lane == 0) {
        float ss = 0.f;
#pragma unroll
        for (int e = 0; e < 8; e++) {
            float v = acc[e] + gb3[e];
            v = v > 0.f ? v : (__expf(v) - 1.f);
            para[(size_t)row * 8 + e] = v;
            ss += v * v;
        }
        wsum[warp] = ss;
    }
    __syncthreads();
    if (tid == 0) {
        float s = 0.f;
        for (int w = 0; w < 8; w++) s += wsum[w];
        partial[blockIdx.x] = s;
    }
}

__global__ void reduce_norm_kernel(const float* __restrict__ partial, float* __restrict__ invnorm) {
    __shared__ float s[256];
    int tid = threadIdx.x;
    float v = 0.f;
    for (int k = 0; k < 8; k++) v += partial[tid + k * 256];
    s[tid] = v;
    __syncthreads();
    for (int off = 128; off; off >>= 1) {
        if (tid < off) s[tid] += s[tid + off];
        __syncthreads();
    }
    if (tid == 0) *invnorm = rsqrtf(s[0]);
}

// ---------------- combine: out = sigmoid(invnorm * sum_e para[b,e]*h3[e,b,m]) ----------------
__global__ void combine_kernel(const float* __restrict__ para, const __nv_bfloat16* __restrict__ h3,
                               const float* __restrict__ invnorm, float* __restrict__ out) {
    int t = blockIdx.x * 256 + threadIdx.x;   // t < B_*128
    int b = t >> 7;
    float inv = *invnorm;
    float4 p0 = ((const float4*)para)[b * 2];
    float4 p1 = ((const float4*)para)[b * 2 + 1];
    float pe[8] = {p0.x, p0.y, p0.z, p0.w, p1.x, p1.y, p1.z, p1.w};
    float acc = 0.f;
#pragma unroll
    for (int e = 0; e < 8; e++)
        acc += pe[e] * __bfloat162float(h3[(size_t)e * B_ * M_OUT + t]);
    float x = acc * inv;
    out[t] = 1.f / (1.f + __expf(-x));
}

// ---------------- host launcher ----------------
extern "C" void kernel_launch(void* const* d_in, const int* in_sizes, int n_in,
                              void* d_out, int out_size) {
    const float* motions = (const float*)d_in[0];
    const float* z       = (const float*)d_in[1];
    const float* gw1     = (const float*)d_in[2];
    const float* gb1     = (const float*)d_in[3];
    const float* gw2     = (const float*)d_in[4];
    const float* gb2     = (const float*)d_in[5];
    const float* gw3     = (const float*)d_in[6];
    const float* gb3     = (const float*)d_in[7];
    const float* W1      = (const float*)d_in[8];
    const float* b1      = (const float*)d_in[9];
    const float* W2      = (const float*)d_in[10];
    const float* b2      = (const float*)d_in[11];
    const float* W3      = (const float*)d_in[12];
    const float* b3      = (const float*)d_in[13];
    float* out = (float*)d_out;

    unsigned char* sc = nullptr;
    cudaGetSymbolAddress((void**)&sc, g_scratch);
    __nv_bfloat16* xpad = (__nv_bfloat16*)(sc + OFF_XPAD);
    __nv_bfloat16* h1e  = (__nv_bfloat16*)(sc + OFF_H1);
    __nv_bfloat16* h2e  = (__nv_bfloat16*)(sc + OFF_H2);
    __nv_bfloat16* g1   = (__nv_bfloat16*)(sc + OFF_G1);
    __nv_bfloat16* g2   = (__nv_bfloat16*)(sc + OFF_G2);
    __nv_bfloat16* h3   = (__nv_bfloat16*)(sc + OFF_H3);
    float* para = (float*)(sc + OFF_PARA);
    float* part = (float*)(sc + OFF_PART);
    float* inv  = (float*)(sc + OFF_INV);
    __nv_bfloat16* gw1t = (__nv_bfloat16*)(sc + OFF_GW1T);
    __nv_bfloat16* gw2t = (__nv_bfloat16*)(sc + OFF_GW2T);
    __nv_bfloat16* W1t  = (__nv_bfloat16*)(sc + OFF_W1T);
    __nv_bfloat16* W2t  = (__nv_bfloat16*)(sc + OFF_W2T);
    __nv_bfloat16* W3t  = (__nv_bfloat16*)(sc + OFF_W3T);

    cudaFuncSetAttribute(gemm_bias_elu, cudaFuncAttributeMaxDynamicSharedMemorySize, SMEM_BYTES);

    const int PREP_T = B_ * (KX + 64);
    prep_kernel<<<(PREP_T + 255) / 256, 256>>>(motions, z, xpad, h1e, h2e);
    wconv_kernel<<<(WC_TOT + 255) / 256, 256>>>(gw1, gw2, W1, W2, W3, gw1t, gw2t, W1t, W2t, W3t);

    dim3 gGate(B_ / 128, 4, 1);
    dim3 gE12(B_ / 128, 4, NE);
    dim3 gE3(B_ / 128, 1, NE);

    // gate MLP
    gemm_bias_elu<<<gGate, 256, SMEM_BYTES>>>(xpad, KX, 0, gw1t, KX, 0, gb1, 0,
                                              g1, H, 0, KX / 64);
    gemm_bias_elu<<<gGate, 256, SMEM_BYTES>>>(g1, H, 0, gw2t, H, 0, gb2, 0,
                                              g2, H, 0, H / 64);
    gate3_kernel<<<B_ / 8, 256>>>(g2, gw3, gb3, para, part);
    reduce_norm_kernel<<<1, 256>>>(part, inv);

    // experts: one batched launch per layer (blockIdx.z = expert)
    gemm_bias_elu<<<gE12, 256, SMEM_BYTES>>>(xpad, KX, 0,
                                             W1t, KX, (size_t)H * KX,
                                             b1, H,
                                             h1e, KH, (size_t)B_ * KH, KX / 64);
    gemm_bias_elu<<<gE12, 256, SMEM_BYTES>>>(h1e, KH, (size_t)B_ * KH,
                                             W2t, KH, (size_t)H * KH,
                                             b2, H,
                                             h2e, KH, (size_t)B_ * KH, KH / 64);
    gemm_bias_elu<<<gE3, 256, SMEM_BYTES>>>(h2e, KH, (size_t)B_ * KH,
                                            W3t, KH, (size_t)M_OUT * KH,
                                            b3, M_OUT,
                                            h3, M_OUT, (size_t)B_ * M_OUT, KH / 64);

    combine_kernel<<<(B_ * M_OUT) / 256, 256>>>(para, h3, inv, out);
}

// round 6
// speedup vs baseline: 1.4021x; 1.0074x over previous
#include <cuda_runtime.h>
#include <cuda_bf16.h>
#include <stdint.h>

// ---------------- problem constants ----------------
static constexpr int B_    = 16384;
static constexpr int KX    = 320;   // padded input K (288 -> 320)
static constexpr int KH    = 576;   // padded hidden K (512 + 32 z + 32 pad)
static constexpr int H     = 512;
static constexpr int M_OUT = 128;
static constexpr int NE    = 8;
static constexpr int NS    = NE + 1; // 8 experts + gate slot

// ---------------- scratch layout (single __device__ array) ----------------
static constexpr size_t OFF_XPAD = 0;
static constexpr size_t SZ_XPAD  = (size_t)B_*KX*2;
static constexpr size_t OFF_H1   = OFF_XPAD + SZ_XPAD;
static constexpr size_t SZ_HEXT  = (size_t)NS*B_*KH*2;      // 9 slots (slot 8 = gate)
static constexpr size_t OFF_H2   = OFF_H1 + SZ_HEXT;
static constexpr size_t OFF_H3   = OFF_H2 + SZ_HEXT;
static constexpr size_t SZ_H3    = (size_t)NE*B_*M_OUT*2;
static constexpr size_t OFF_PARA = OFF_H3 + SZ_H3;
static constexpr size_t SZ_PARA  = (size_t)B_*NE*4;
static constexpr size_t OFF_PART = OFF_PARA + SZ_PARA;
static constexpr size_t SZ_PART  = 2048*4;
static constexpr size_t OFF_INV  = OFF_PART + SZ_PART;
static constexpr size_t SZ_INV   = 256;
static constexpr size_t OFF_W1T  = OFF_INV + SZ_INV;
static constexpr size_t SZ_W1T   = (size_t)NS*H*KX*2;
static constexpr size_t OFF_W2T  = OFF_W1T + SZ_W1T;
static constexpr size_t SZ_W2T   = (size_t)NS*H*KH*2;
static constexpr size_t OFF_W3T  = OFF_W2T + SZ_W2T;
static constexpr size_t SZ_W3T   = (size_t)NE*M_OUT*KH*2;
static constexpr size_t OFF_B1A  = OFF_W3T + SZ_W3T;
static constexpr size_t SZ_B1A   = (size_t)NS*H*4;
static constexpr size_t OFF_B2A  = OFF_B1A + SZ_B1A;
static constexpr size_t SZ_B2A   = (size_t)NS*H*4;
static constexpr size_t SCRATCH_TOTAL = OFF_B2A + SZ_B2A;

__device__ __align__(1024) unsigned char g_scratch[SCRATCH_TOTAL];

// ---------------- helpers ----------------
__device__ __forceinline__ uint32_t smem_u32(const void* p) {
    return (uint32_t)__cvta_generic_to_shared(p);
}
__device__ __forceinline__ uint32_t swz128(uint32_t off) {
    return off ^ ((off >> 3) & 0x70);
}
__device__ __forceinline__ void cp16(uint32_t dst, const void* src) {
    asm volatile("cp.async.cg.shared.global [%0], [%1], 16;\n" :: "r"(dst), "l"(src) : "memory");
}
__device__ __forceinline__ void ldsm_x4(uint32_t& r0, uint32_t& r1, uint32_t& r2, uint32_t& r3,
                                        uint32_t addr) {
    asm volatile("ldmatrix.sync.aligned.m8n8.x4.shared.b16 {%0,%1,%2,%3}, [%4];"
                 : "=r"(r0), "=r"(r1), "=r"(r2), "=r"(r3) : "r"(addr));
}
__device__ __forceinline__ void mma16816(float* c, uint32_t a0, uint32_t a1, uint32_t a2, uint32_t a3,
                                         uint32_t b0, uint32_t b1) {
    asm volatile(
        "mma.sync.aligned.m16n8k16.row.col.f32.bf16.bf16.f32 "
        "{%0,%1,%2,%3}, {%4,%5,%6,%7}, {%8,%9}, {%0,%1,%2,%3};"
        : "+f"(c[0]), "+f"(c[1]), "+f"(c[2]), "+f"(c[3])
        : "r"(a0), "r"(a1), "r"(a2), "r"(a3), "r"(b0), "r"(b1));
}

// ---------------- prep kernel ----------------
// xpad[B,KX] = concat(motions, z, 0-pad); z-columns [512:576) of expert slots 0..7
// of h1e/h2e. Gate slot (8) z-cols stay zero (device global zero-init, never written)
// and are multiplied by zero weight rows anyway.
__global__ void prep_kernel(const float* __restrict__ motions, const float* __restrict__ z,
                            __nv_bfloat16* __restrict__ xpad,
                            __nv_bfloat16* __restrict__ h1e, __nv_bfloat16* __restrict__ h2e) {
    int idx = blockIdx.x * 256 + threadIdx.x;
    const int XT = B_ * KX;
    const int ZT = B_ * 64;
    if (idx < XT) {
        int row = idx / KX, c = idx % KX;
        float v = 0.f;
        if (c < 256)      v = motions[(size_t)row * 256 + c];
        else if (c < 288) v = z[(size_t)row * 32 + (c - 256)];
        xpad[idx] = __float2bfloat16(v);
    } else if (idx < XT + ZT) {
        int j = idx - XT;
        int row = j / 64, c = j % 64;
        __nv_bfloat16 v = __float2bfloat16(c < 32 ? z[(size_t)row * 32 + c] : 0.f);
        size_t base = (size_t)row * KH + 512 + c;
#pragma unroll
        for (int e = 0; e < NE; e++) {
            h1e[(size_t)e * B_ * KH + base] = v;
            h2e[(size_t)e * B_ * KH + base] = v;
        }
    }
}

// ---------------- weight convert/transpose/pad kernel ----------------
static constexpr int WC_C0 = NS * H * KX;       // W1t (slot 8 = gate gw1)
static constexpr int WC_C1 = NS * H * KH;       // W2t (slot 8 = gate gw2, K padded)
static constexpr int WC_C2 = NE * M_OUT * KH;   // W3t
static constexpr int WC_C3 = NS * H;            // b1arr
static constexpr int WC_C4 = NS * H;            // b2arr
static constexpr int WC_TOT = WC_C0 + WC_C1 + WC_C2 + WC_C3 + WC_C4;

__global__ void wconv_kernel(const float* __restrict__ gw1, const float* __restrict__ gw2,
                             const float* __restrict__ W1, const float* __restrict__ W2,
                             const float* __restrict__ W3,
                             const float* __restrict__ gb1, const float* __restrict__ gb2,
                             const float* __restrict__ b1, const float* __restrict__ b2,
                             __nv_bfloat16* __restrict__ W1t, __nv_bfloat16* __restrict__ W2t,
                             __nv_bfloat16* __restrict__ W3t,
                             float* __restrict__ b1a, float* __restrict__ b2a) {
    int idx = blockIdx.x * 256 + threadIdx.x;
    if (idx < WC_C0) {
        int e = idx / (H * KX); int r = idx % (H * KX); int n = r / KX, k = r % KX;
        float v = 0.f;
        if (e < NE) { if (k < 288) v = W1[((size_t)e * 288 + k) * H + n]; }
        else        { if (k < 288) v = gw1[(size_t)k * H + n]; }
        W1t[idx] = __float2bfloat16(v);
        return;
    }
    idx -= WC_C0;
    if (idx < WC_C1) {
        int e = idx / (H * KH); int r = idx % (H * KH); int n = r / KH, k = r % KH;
        float v = 0.f;
        if (e < NE) { if (k < 544) v = W2[((size_t)e * 544 + k) * H + n]; }
        else        { if (k < 512) v = gw2[(size_t)k * H + n]; }
        W2t[idx] = __float2bfloat16(v);
        return;
    }
    idx -= WC_C1;
    if (idx < WC_C2) {
        int e = idx / (M_OUT * KH); int r = idx % (M_OUT * KH); int n = r / KH, k = r % KH;
        W3t[idx] = __float2bfloat16(k < 544 ? W3[((size_t)e * 544 + k) * M_OUT + n] : 0.f);
        return;
    }
    idx -= WC_C2;
    if (idx < WC_C3) {
        int e = idx / H, n = idx % H;
        b1a[idx] = (e < NE) ? b1[(size_t)e * H + n] : gb1[n];
        return;
    }
    idx -= WC_C3;
    if (idx < WC_C4) {
        int e = idx / H, n = idx % H;
        b2a[idx] = (e < NE) ? b2[(size_t)e * H + n] : gb2[n];
    }
}

// ---------------- HMMA GEMM: C[m,n] = elu(sum_k A[m,k]*Bt[n,k] + bias[n]) -> bf16 ----------------
// 256 threads, tile 128x128, K-chunks of 64, 3-stage cp.async ring, 2 CTAs/SM.
// Warps 2(M) x 4(N); warp tile 64x32. Inner loop: fragment double-buffer (prefetch kk+1
// LDSMs before kk MMAs) + XOR-based swizzled addressing.
static constexpr int STAGE_BYTES = 16384 + 16384;
static constexpr int NSTAGE      = 3;
static constexpr int SMEM_BYTES  = 1024 + NSTAGE * STAGE_BYTES; // 99328

__global__ __launch_bounds__(256, 2)
void gemm_bias_elu(const __nv_bfloat16* __restrict__ A, int lda, size_t a_es,
                   const __nv_bfloat16* __restrict__ Bw, int ldb, size_t b_es,
                   const float* __restrict__ bias, int bias_es,
                   __nv_bfloat16* __restrict__ C, int ldc, size_t c_es, int kchunks) {
    extern __shared__ unsigned char smem[];
    float* sbias = (float*)smem;
    unsigned char* tiles = smem + 1024;
    const uint32_t tiles_u = smem_u32(tiles);
    const int tid = threadIdx.x;
    const int e  = blockIdx.z;
    const int m0 = blockIdx.x * 128, n0 = blockIdx.y * 128;
    A    += (size_t)e * a_es;
    Bw   += (size_t)e * b_es;
    bias += (size_t)e * bias_es;
    C    += (size_t)e * c_es;

    if (tid < 128) sbias[tid] = bias[n0 + tid];

    // --- loader: each thread owns 4 consecutive 16B segs of one row per tile ---
    const int lr = tid >> 1;                 // row 0..127
    const uint32_t lbase = (tid & 1) * 64;   // 0 or 64 (byte)
    const char* gA = (const char*)A + ((size_t)(m0 + lr) * lda) * 2 + lbase;
    const char* gB = (const char*)Bw + ((size_t)(n0 + lr) * ldb) * 2 + lbase;
    const uint32_t su   = (uint32_t)lr * 128 + lbase;
    const uint32_t sxor = (su >> 3) & 0x70;

    auto load_stage = [&](int s, int buf) {
        uint32_t ab = tiles_u + buf * STAGE_BYTES;
        uint32_t bb = ab + 16384;
        const char* a = gA + (size_t)s * 128;
        const char* b = gB + (size_t)s * 128;
#pragma unroll
        for (int i = 0; i < 4; i++) {
            uint32_t so = (su + i * 16) ^ sxor;
            cp16(ab + so, a + i * 16);
            cp16(bb + so, b + i * 16);
        }
        asm volatile("cp.async.commit_group;" ::: "memory");
    };

    load_stage(0, 0);
    load_stage(1, 1);

    const int lane = tid & 31, w = tid >> 5;
    const int wm = (w >> 2) * 64;
    const int wn = (w & 3) * 32;
    const int arow = lane & 15, ahalf = (lane >> 4) * 16;

    // Precomputed swizzled base offsets (kk=0). kk advances via XOR with kk*32:
    // valid because bits 5-6 of the base are zero (ahalf is only bit 4) and the
    // swizzle XOR bits depend only on row bits (>=7).
    uint32_t pa[4], pb[2];
#pragma unroll
    for (int mf = 0; mf < 4; mf++)
        pa[mf] = swz128((uint32_t)((wm + mf * 16 + arow) * 128 + ahalf));
#pragma unroll
    for (int p = 0; p < 2; p++)
        pb[p] = swz128((uint32_t)((wn + p * 16 + arow) * 128 + ahalf));

    float acc[4][4][4];
#pragma unroll
    for (int mf = 0; mf < 4; mf++)
#pragma unroll
        for (int nf = 0; nf < 4; nf++)
#pragma unroll
            for (int i = 0; i < 4; i++) acc[mf][nf][i] = 0.f;

    int buf = 0, nbuf = 2;
    for (int s = 0; s < kchunks; s++) {
        asm volatile("cp.async.wait_group 1;" ::: "memory");
        __syncthreads();
        if (s + 2 < kchunks) load_stage(s + 2, nbuf);
        else asm volatile("cp.async.commit_group;" ::: "memory");

        uint32_t abase = tiles_u + buf * STAGE_BYTES;
        uint32_t bbase = abase + 16384;

        uint32_t af[2][4][4], bf[2][2][4];
        // preload kk = 0
#pragma unroll
        for (int mf = 0; mf < 4; mf++)
            ldsm_x4(af[0][mf][0], af[0][mf][1], af[0][mf][2], af[0][mf][3], abase + pa[mf]);
#pragma unroll
        for (int p = 0; p < 2; p++)
            ldsm_x4(bf[0][p][0], bf[0][p][1], bf[0][p][2], bf[0][p][3], bbase + pb[p]);

#pragma unroll
        for (int kk = 0; kk < 4; kk++) {
            const int cur = kk & 1, nxt = cur ^ 1;
            if (kk < 3) {
                const uint32_t kx = (uint32_t)((kk + 1) * 32);
#pragma unroll
                for (int mf = 0; mf < 4; mf++)
                    ldsm_x4(af[nxt][mf][0], af[nxt][mf][1], af[nxt][mf][2], af[nxt][mf][3],
                            abase + (pa[mf] ^ kx));
#pragma unroll
                for (int p = 0; p < 2; p++)
                    ldsm_x4(bf[nxt][p][0], bf[nxt][p][1], bf[nxt][p][2], bf[nxt][p][3],
                            bbase + (pb[p] ^ kx));
            }
#pragma unroll
            for (int mf = 0; mf < 4; mf++) {
#pragma unroll
                for (int p = 0; p < 2; p++) {
                    mma16816(acc[mf][2 * p],     af[cur][mf][0], af[cur][mf][1],
                             af[cur][mf][2], af[cur][mf][3], bf[cur][p][0], bf[cur][p][2]);
                    mma16816(acc[mf][2 * p + 1], af[cur][mf][0], af[cur][mf][1],
                             af[cur][mf][2], af[cur][mf][3], bf[cur][p][1], bf[cur][p][3]);
                }
            }
        }
        buf = (buf == 2) ? 0 : buf + 1;
        nbuf = (nbuf == 2) ? 0 : nbuf + 1;
    }

    // ---- epilogue: bias + ELU + bf16 store ----
    const int cg = lane >> 2;
    const int cc = (lane & 3) * 2;
#pragma unroll
    for (int mf = 0; mf < 4; mf++) {
        int r0 = m0 + wm + mf * 16 + cg;
        int r1 = r0 + 8;
#pragma unroll
        for (int nf = 0; nf < 4; nf++) {
            int col = wn + nf * 8 + cc;
            float b0 = sbias[col], b1v = sbias[col + 1];
            float v0 = acc[mf][nf][0] + b0, v1 = acc[mf][nf][1] + b1v;
            float v2 = acc[mf][nf][2] + b0, v3 = acc[mf][nf][3] + b1v;
            v0 = v0 > 0.f ? v0 : (__expf(v0) - 1.f);
            v1 = v1 > 0.f ? v1 : (__expf(v1) - 1.f);
            v2 = v2 > 0.f ? v2 : (__expf(v2) - 1.f);
            v3 = v3 > 0.f ? v3 : (__expf(v3) - 1.f);
            *(__nv_bfloat162*)(C + (size_t)r0 * ldc + n0 + col) = __floats2bfloat162_rn(v0, v1);
            *(__nv_bfloat162*)(C + (size_t)r1 * ldc + n0 + col) = __floats2bfloat162_rn(v2, v3);
        }
    }
}

// ---------------- gate layer 3 (N=8) + deterministic partial norm ----------------
// g2 rows live in h2e slot 8 with row stride KH (first 512 cols valid).
__global__ void gate3_kernel(const __nv_bfloat16* __restrict__ g2,
                             const float* __restrict__ gw3, const float* __restrict__ gb3,
                             float* __restrict__ para, float* __restrict__ partial) {
    __shared__ float sw[8 * 512];
    __shared__ float wsum[8];
    int tid = threadIdx.x;
    for (int i = tid; i < 4096; i += 256) { int k = i / 8, e = i % 8; sw[e * 512 + k] = gw3[k * 8 + e]; }
    __syncthreads();
    int warp = tid / 32, lane = tid % 32;
    int row = blockIdx.x * 8 + warp;
    float acc[8];
#pragma unroll
    for (int e = 0; e < 8; e++) acc[e] = 0.f;
    const __nv_bfloat162* gr = (const __nv_bfloat162*)(g2 + (size_t)row * KH);
#pragma unroll
    for (int i = 0; i < 8; i++) {
        __nv_bfloat162 p = gr[i * 32 + lane];
        float a0 = __bfloat162float(p.x), a1 = __bfloat162float(p.y);
        int k0 = i * 64 + lane * 2;
#pragma unroll
        for (int e = 0; e < 8; e++) acc[e] += a0 * sw[e * 512 + k0] + a1 * sw[e * 512 + k0 + 1];
    }
#pragma unroll
    for (int off = 16; off; off >>= 1)
#pragma unroll
        for (int e = 0; e < 8; e++) acc[e] += __shfl_down_sync(0xFFFFFFFFu, acc[e], off);
    if (lane == 0) {
        float ss = 0.f;
#pragma unroll
        for (int e = 0; e < 8; e++) {
            float v = acc[e] + gb3[e];
            v = v > 0.f ? v : (__expf(v) - 1.f);
            para[(size_t)row * 8 + e] = v;
            ss += v * v;
        }
        wsum[warp] = ss;
    }
    __syncthreads();
    if (tid == 0) {
        float s = 0.f;
        for (int w = 0; w < 8; w++) s += wsum[w];
        partial[blockIdx.x] = s;
    }
}

__global__ void reduce_norm_kernel(const float* __restrict__ partial, float* __restrict__ invnorm) {
    __shared__ float s[256];
    int tid = threadIdx.x;
    float v = 0.f;
    for (int k = 0; k < 8; k++) v += partial[tid + k * 256];
    s[tid] = v;
    __syncthreads();
    for (int off = 128; off; off >>= 1) {
        if (tid < off) s[tid] += s[tid + off];
        __syncthreads();
    }
    if (tid == 0) *invnorm = rsqrtf(s[0]);
}

// ---------------- combine ----------------
__global__ void combine_kernel(const float* __restrict__ para, const __nv_bfloat16* __restrict__ h3,
                               const float* __restrict__ invnorm, float* __restrict__ out) {
    int t = blockIdx.x * 256 + threadIdx.x;
    int b = t >> 7;
    float inv = *invnorm;
    float4 p0 = ((const float4*)para)[b * 2];
    float4 p1 = ((const float4*)para)[b * 2 + 1];
    float pe[8] = {p0.x, p0.y, p0.z, p0.w, p1.x, p1.y, p1.z, p1.w};
    float acc = 0.f;
#pragma unroll
    for (int e = 0; e < 8; e++)
        acc += pe[e] * __bfloat162float(h3[(size_t)e * B_ * M_OUT + t]);
    float x = acc * inv;
    out[t] = 1.f / (1.f + __expf(-x));
}

// ---------------- host launcher ----------------
extern "C" void kernel_launch(void* const* d_in, const int* in_sizes, int n_in,
                              void* d_out, int out_size) {
    const float* motions = (const float*)d_in[0];
    const float* z       = (const float*)d_in[1];
    const float* gw1     = (const float*)d_in[2];
    const float* gb1     = (const float*)d_in[3];
    const float* gw2     = (const float*)d_in[4];
    const float* gb2     = (const float*)d_in[5];
    const float* gw3     = (const float*)d_in[6];
    const float* gb3     = (const float*)d_in[7];
    const float* W1      = (const float*)d_in[8];
    const float* b1      = (const float*)d_in[9];
    const float* W2      = (const float*)d_in[10];
    const float* b2      = (const float*)d_in[11];
    const float* W3      = (const float*)d_in[12];
    const float* b3      = (const float*)d_in[13];
    float* out = (float*)d_out;

    unsigned char* sc = nullptr;
    cudaGetSymbolAddress((void**)&sc, g_scratch);
    __nv_bfloat16* xpad = (__nv_bfloat16*)(sc + OFF_XPAD);
    __nv_bfloat16* h1e  = (__nv_bfloat16*)(sc + OFF_H1);
    __nv_bfloat16* h2e  = (__nv_bfloat16*)(sc + OFF_H2);
    __nv_bfloat16* h3   = (__nv_bfloat16*)(sc + OFF_H3);
    float* para = (float*)(sc + OFF_PARA);
    float* part = (float*)(sc + OFF_PART);
    float* inv  = (float*)(sc + OFF_INV);
    __nv_bfloat16* W1t  = (__nv_bfloat16*)(sc + OFF_W1T);
    __nv_bfloat16* W2t  = (__nv_bfloat16*)(sc + OFF_W2T);
    __nv_bfloat16* W3t  = (__nv_bfloat16*)(sc + OFF_W3T);
    float* b1a = (float*)(sc + OFF_B1A);
    float* b2a = (float*)(sc + OFF_B2A);

    cudaFuncSetAttribute(gemm_bias_elu, cudaFuncAttributeMaxDynamicSharedMemorySize, SMEM_BYTES);

    const int PREP_T = B_ * (KX + 64);
    prep_kernel<<<(PREP_T + 255) / 256, 256>>>(motions, z, xpad, h1e, h2e);
    wconv_kernel<<<(WC_TOT + 255) / 256, 256>>>(gw1, gw2, W1, W2, W3, gb1, gb2, b1, b2,
                                                W1t, W2t, W3t, b1a, b2a);

    dim3 gL12(B_ / 128, 4, NS);   // 9 z-slices: experts 0..7 + gate
    dim3 gL3(B_ / 128, 1, NE);

    // Layer 1: out slot e of h1e (gate -> slot 8)
    gemm_bias_elu<<<gL12, 256, SMEM_BYTES>>>(xpad, KX, 0,
                                             W1t, KX, (size_t)H * KX,
                                             b1a, H,
                                             h1e, KH, (size_t)B_ * KH, KX / 64);
    // Layer 2
    gemm_bias_elu<<<gL12, 256, SMEM_BYTES>>>(h1e, KH, (size_t)B_ * KH,
                                             W2t, KH, (size_t)H * KH,
                                             b2a, H,
                                             h2e, KH, (size_t)B_ * KH, KH / 64);
    // gate layer 3 + norm (reads h2e slot 8)
    gate3_kernel<<<B_ / 8, 256>>>(h2e + (size_t)NE * B_ * KH, gw3, gb3, para, part);
    reduce_norm_kernel<<<1, 256>>>(part, inv);

    // Layer 3 (experts only)
    gemm_bias_elu<<<gL3, 256, SMEM_BYTES>>>(h2e, KH, (size_t)B_ * KH,
                                            W3t, KH, (size_t)M_OUT * KH,
                                            b3, M_OUT,
                                            h3, M_OUT, (size_t)B_ * M_OUT, KH / 64);

    combine_kernel<<<(B_ * M_OUT) / 256, 256>>>(para, h3, inv, out);
}